// round 6
// baseline (speedup 1.0000x reference)
#include <cuda_runtime.h>
#include <cuda_fp16.h>
#include <mma.h>
#include <cstdint>

// ===================== arch gating =====================
// The harness compiles both a compute_103 (non-'a') pass and an sm_103a pass.
// tcgen05 only exists under the arch-specific ('a') target, so gate on the
// feature macros; the non-'a' pass gets a WMMA fallback with the SAME kernel
// symbol + launch config, keeping host code path-agnostic.
#if !defined(__CUDA_ARCH__) \
    || defined(__CUDA_ARCH_FEAT_SM103_ALL) || defined(__CUDA_ARCH_FEAT_SM101_ALL) \
    || defined(__CUDA_ARCH_FEAT_SM100_ALL) \
    || (defined(__CUDA_ARCH_SPECIFIC__) && (__CUDA_ARCH_SPECIFIC__ >= 1000))
#define USE_TCGEN05 1
#else
#define USE_TCGEN05 0
#endif

// ===================== problem constants =====================
static constexpr int TT = 64;     // positions (grouped axis)
static constexpr int DD = 256;    // model dim
static constexpr int HH = 1024;   // hidden dim
static constexpr int MTILE = 128; // rows per CTA
static constexpr int NC = 64;     // H-chunk per step
static constexpr int CHUNKS = HH / NC; // 16

// fp16 transposed weight scratch (static device arrays are allowed)
__device__ __align__(16) __half g_W1T[(size_t)TT * HH * DD]; // [T,H,D]
__device__ __align__(16) __half g_W2T[(size_t)TT * DD * HH]; // [T,D,H]

// ===================== smem layout (bytes) — tcgen05 path =====================
static constexpr int SM_X    = 0;        // 128x256 f16 SW128 blocked = 64KB
static constexpr int SM_W1_0 = 65536;    // 64x256 f16 = 32KB
static constexpr int SM_W1_1 = 98304;
static constexpr int SM_W2_0 = 131072;   // 256x64 f16 = 32KB
static constexpr int SM_W2_1 = 163840;
static constexpr int SM_B1   = 196608;   // 1024 f32
static constexpr int SM_B2   = 200704;   // 256 f32
static constexpr int SM_TMEMP= 201728;
static constexpr int MB_G1   = 201736;
static constexpr int MB_G2   = 201744;
static constexpr int SMEM_BYTES = 201760;

// fallback layout (fits inside SMEM_BYTES)
static constexpr int FB_X   = 0;        // 128x256 f16 row-major = 64KB
static constexpr int FB_H   = 65536;    // 128x80 f16 row-major  = 20480
static constexpr int FB_STG = 86016;    // 8 warps x 16x24 f32   = 12288

// TMEM columns
static constexpr int TM_OUT = 0;    // 256 cols f32
static constexpr int TM_H   = 256;  // 64 cols f32
static constexpr int TM_A2  = 320;  // 32 cols f16x2

// idesc kind::f16: f16 in (atype=btype=0), f32 accum (bit4), N>>3 @17, M>>4 @24
static constexpr uint32_t IDESC1 = (1u << 4) | ((NC / 8) << 17) | ((MTILE / 16) << 24);
static constexpr uint32_t IDESC2 = (1u << 4) | ((DD / 8) << 17) | ((MTILE / 16) << 24);

// SW128 K-major smem descriptor base (LBO=1, SBO=64, version=1, SW128)
static constexpr uint64_t DESC_BASE =
    (2ull << 61) | (1ull << 46) | (64ull << 32) | (1ull << 16);

// ===================== portable helpers =====================
__device__ __forceinline__ uint32_t smem_u32(const void* p) {
    return (uint32_t)__cvta_generic_to_shared(p);
}
__device__ __forceinline__ bool elect_one() {
    uint32_t pred;
    asm volatile("{\n\t.reg .pred p;\n\telect.sync _|p, 0xFFFFFFFF;\n\tselp.b32 %0,1,0,p;\n\t}"
                 : "=r"(pred));
    return pred != 0;
}
#define MBAR_INIT(addr, cnt) \
    asm volatile("mbarrier.init.shared.b64 [%0], %1;" :: "r"(addr), "r"((uint32_t)(cnt)) : "memory")
#define MBAR_WAIT(addr, parity) do {                                              \
    uint32_t _m = (addr); uint32_t _p = (uint32_t)(parity); uint32_t _d;          \
    asm volatile("{\n\t.reg .pred p;\n\t"                                         \
        "mbarrier.try_wait.parity.acquire.cta.shared::cta.b64 p, [%1], %2;\n\t"   \
        "selp.b32 %0,1,0,p;\n\t}" : "=r"(_d) : "r"(_m), "r"(_p) : "memory");      \
    if (!_d) {                                                                    \
        asm volatile("{\n\t.reg .pred P1;\n\t"                                    \
            "WL_%=:\n\t"                                                          \
            "mbarrier.try_wait.parity.acquire.cta.shared::cta.b64 P1, [%0], %1, 0x989680;\n\t" \
            "@P1 bra.uni WD_%=;\n\tbra.uni WL_%=;\n\tWD_%=:\n\t}"                 \
            :: "r"(_m), "r"(_p) : "memory");                                      \
    }                                                                             \
} while (0)
#define FENCE_ASYNC() asm volatile("fence.proxy.async.shared::cta;" ::: "memory")

__device__ __forceinline__ uint32_t sw128(uint32_t off) { return off ^ ((off >> 3) & 0x70); }

#if USE_TCGEN05
// ===================== tcgen05-only PTX helpers =====================
#define TCF_BEFORE()  asm volatile("tcgen05.fence::before_thread_sync;" ::: "memory")
#define TCF_AFTER()   asm volatile("tcgen05.fence::after_thread_sync;" ::: "memory")
#define TC_WAITLD()   asm volatile("tcgen05.wait::ld.sync.aligned;" ::: "memory")
#define TC_WAITST()   asm volatile("tcgen05.wait::st.sync.aligned;" ::: "memory")
#define TC_ALLOC(sa, n)  asm volatile("tcgen05.alloc.cta_group::1.sync.aligned.shared::cta.b32 [%0], %1;" :: "r"(sa), "r"((uint32_t)(n)) : "memory")
#define TC_DEALLOC(a, n) asm volatile("tcgen05.dealloc.cta_group::1.sync.aligned.b32 %0, %1;" :: "r"(a), "r"((uint32_t)(n)))
#define TC_RELINQ()      asm volatile("tcgen05.relinquish_alloc_permit.cta_group::1.sync.aligned;")
#define TC_COMMIT(mb)    asm volatile("tcgen05.commit.cta_group::1.mbarrier::arrive::one.shared::cluster.b64 [%0];" :: "r"(mb) : "memory")

__device__ __forceinline__ void mma_f16_ss(uint32_t d, uint64_t ad, uint64_t bd,
                                           uint32_t idesc, uint32_t en) {
    asm volatile("{\n\t.reg .pred p;\n\tsetp.ne.u32 p, %5, 0;\n\t"
                 "tcgen05.mma.cta_group::1.kind::f16 [%0], %1, %2, %3, {%4,%4,%4,%4}, p;\n\t}"
                 :: "r"(d), "l"(ad), "l"(bd), "r"(idesc), "r"(0u), "r"(en) : "memory");
}
__device__ __forceinline__ void mma_f16_ts(uint32_t d, uint32_t a, uint64_t bd,
                                           uint32_t idesc, uint32_t en) {
    asm volatile("{\n\t.reg .pred p;\n\tsetp.ne.u32 p, %5, 0;\n\t"
                 "tcgen05.mma.cta_group::1.kind::f16 [%0], [%1], %2, %3, {%4,%4,%4,%4}, p;\n\t}"
                 :: "r"(d), "r"(a), "l"(bd), "r"(idesc), "r"(0u), "r"(en) : "memory");
}

#define LDTM32(r, addr) \
    asm volatile("tcgen05.ld.sync.aligned.32x32b.x32.b32 " \
        "{%0,%1,%2,%3,%4,%5,%6,%7,%8,%9,%10,%11,%12,%13,%14,%15," \
        "%16,%17,%18,%19,%20,%21,%22,%23,%24,%25,%26,%27,%28,%29,%30,%31}, [%32];" \
        : "=r"((r)[0]),"=r"((r)[1]),"=r"((r)[2]),"=r"((r)[3]),"=r"((r)[4]),"=r"((r)[5]),"=r"((r)[6]),"=r"((r)[7]), \
          "=r"((r)[8]),"=r"((r)[9]),"=r"((r)[10]),"=r"((r)[11]),"=r"((r)[12]),"=r"((r)[13]),"=r"((r)[14]),"=r"((r)[15]), \
          "=r"((r)[16]),"=r"((r)[17]),"=r"((r)[18]),"=r"((r)[19]),"=r"((r)[20]),"=r"((r)[21]),"=r"((r)[22]),"=r"((r)[23]), \
          "=r"((r)[24]),"=r"((r)[25]),"=r"((r)[26]),"=r"((r)[27]),"=r"((r)[28]),"=r"((r)[29]),"=r"((r)[30]),"=r"((r)[31]) \
        : "r"(addr))
#define STTM32(addr, r) \
    asm volatile("tcgen05.st.sync.aligned.32x32b.x32.b32 [%0], " \
        "{%1,%2,%3,%4,%5,%6,%7,%8,%9,%10,%11,%12,%13,%14,%15,%16," \
        "%17,%18,%19,%20,%21,%22,%23,%24,%25,%26,%27,%28,%29,%30,%31,%32};" \
        :: "r"(addr), \
           "r"((r)[0]),"r"((r)[1]),"r"((r)[2]),"r"((r)[3]),"r"((r)[4]),"r"((r)[5]),"r"((r)[6]),"r"((r)[7]), \
           "r"((r)[8]),"r"((r)[9]),"r"((r)[10]),"r"((r)[11]),"r"((r)[12]),"r"((r)[13]),"r"((r)[14]),"r"((r)[15]), \
           "r"((r)[16]),"r"((r)[17]),"r"((r)[18]),"r"((r)[19]),"r"((r)[20]),"r"((r)[21]),"r"((r)[22]),"r"((r)[23]), \
           "r"((r)[24]),"r"((r)[25]),"r"((r)[26]),"r"((r)[27]),"r"((r)[28]),"r"((r)[29]),"r"((r)[30]),"r"((r)[31]) \
        : "memory")
#endif // USE_TCGEN05

// ===================== pre-pass: transpose + fp32->fp16 =====================
__device__ __forceinline__ void transpose_body(const float* __restrict__ src,
                                               __half* __restrict__ dst, int R, int C) {
    __shared__ float tile[32][33];
    int t  = blockIdx.z;
    int c0 = blockIdx.x * 32, r0 = blockIdx.y * 32;
    int tx = threadIdx.x, ty = threadIdx.y;
    const float* s = src + (size_t)t * R * C;
    __half* d = dst + (size_t)t * R * C;
#pragma unroll
    for (int j = 0; j < 32; j += 8)
        tile[ty + j][tx] = s[(size_t)(r0 + ty + j) * C + (c0 + tx)];
    __syncthreads();
#pragma unroll
    for (int j = 0; j < 32; j += 8)
        d[(size_t)(c0 + ty + j) * R + (r0 + tx)] = __float2half_rn(tile[tx][ty + j]);
}
__global__ void tconvW1(const float* __restrict__ src) { transpose_body(src, g_W1T, DD, HH); }
__global__ void tconvW2(const float* __restrict__ src) { transpose_body(src, g_W2T, HH, DD); }

#if USE_TCGEN05
// ===================== weight-chunk loader (all 256 threads) =====================
__device__ __forceinline__ void load_chunk(char* smem, int t, int j, int tid) {
    const int sl = j & 1;
    // W1T chunk: 64 rows (n=h-local), K=256 halfs contiguous
    const __half* w1src = g_W1T + ((size_t)t * HH + (size_t)j * NC) * DD;
    char* dst1 = smem + (sl ? SM_W1_1 : SM_W1_0);
    for (int idx = tid; idx < 2048; idx += 256) {
        int n = idx >> 5, k = (idx & 31) * 8;
        uint4 v = *(const uint4*)(w1src + (size_t)n * DD + k);
        uint32_t off = (uint32_t)(((n >> 3) + (k >> 6) * 8) * 1024 + (n & 7) * 128 + (k & 63) * 2);
        *(uint4*)(dst1 + sw128(off)) = v;
    }
    // W2T chunk: 256 rows (n=d), K=64 halfs at offset j*64 within row
    const __half* w2src = g_W2T + (size_t)t * DD * HH + (size_t)j * NC;
    char* dst2 = smem + (sl ? SM_W2_1 : SM_W2_0);
    for (int idx = tid; idx < 2048; idx += 256) {
        int n = idx >> 3, k = (idx & 7) * 8;
        uint4 v = *(const uint4*)(w2src + (size_t)n * HH + k);
        uint32_t off = (uint32_t)((n >> 3) * 1024 + (n & 7) * 128 + k * 2);
        *(uint4*)(dst2 + sw128(off)) = v;
    }
}
#endif

// ===================== fused grouped-MLP kernel =====================
__global__ void __launch_bounds__(256, 1)
fused_mlp(const float* __restrict__ x, const float* __restrict__ b1,
          const float* __restrict__ b2, float* __restrict__ out) {
#if USE_TCGEN05
    // ---------------- tcgen05 / TMEM path (sm_103a cubin) ----------------
    extern __shared__ __align__(1024) char smem[];
    const int tid = threadIdx.x;
    const int wid = tid >> 5;
    const int t     = blockIdx.x >> 5;   // 32 consecutive CTAs share t
    const int mtile = blockIdx.x & 31;
    const uint32_t sb = smem_u32(smem);

    if (tid == 0) { MBAR_INIT(sb + MB_G1, 1); MBAR_INIT(sb + MB_G2, 1); }
    if (wid == 4) { TC_ALLOC(sb + SM_TMEMP, 512); TC_RELINQ(); }

    // stage x tile (fp32->fp16, SW128 blocked atoms), biases, chunk-0 weights
    {
        const size_t bbase = (size_t)mtile * MTILE;
        for (int idx = tid; idx < MTILE * DD / 4; idx += 256) {
            int r = idx >> 6;
            int k = (idx & 63) * 4;
            float4 v = *(const float4*)(x + ((bbase + r) * TT + t) * DD + k);
            __half2 h0 = __floats2half2_rn(v.x, v.y);
            __half2 h1 = __floats2half2_rn(v.z, v.w);
            uint32_t off = (uint32_t)(((r >> 3) + (k >> 6) * 16) * 1024 + (r & 7) * 128 + (k & 63) * 2);
            uint2 pk; pk.x = *(uint32_t*)&h0; pk.y = *(uint32_t*)&h1;
            *(uint2*)(smem + SM_X + sw128(off)) = pk;
        }
        for (int idx = tid; idx < HH; idx += 256)
            ((float*)(smem + SM_B1))[idx] = b1[(size_t)t * HH + idx];
        for (int idx = tid; idx < DD; idx += 256)
            ((float*)(smem + SM_B2))[idx] = b2[(size_t)t * DD + idx];
        load_chunk(smem, t, 0, tid);
    }
    FENCE_ASYNC();
    __syncthreads();
    uint32_t tmem;
    asm volatile("ld.shared.b32 %0, [%1];" : "=r"(tmem) : "r"(sb + SM_TMEMP));

    const float* b1s = (const float*)(smem + SM_B1);
    const float* b2s = (const float*)(smem + SM_B2);
    const uint64_t adesc = DESC_BASE | (((uint64_t)(sb + SM_X)    >> 4) & 0x3FFF);
    const uint64_t w1d0  = DESC_BASE | (((uint64_t)(sb + SM_W1_0) >> 4) & 0x3FFF);
    const uint64_t w1d1  = DESC_BASE | (((uint64_t)(sb + SM_W1_1) >> 4) & 0x3FFF);
    const uint64_t w2d0  = DESC_BASE | (((uint64_t)(sb + SM_W2_0) >> 4) & 0x3FFF);
    const uint64_t w2d1  = DESC_BASE | (((uint64_t)(sb + SM_W2_1) >> 4) & 0x3FFF);
    const uint32_t warpoff = (uint32_t)wid << 21;

#pragma unroll 1
    for (int i = 0; i < CHUNKS; ++i) {
        const int s = i & 1;
        // 1) GEMM1(i): h[128,64] = X[128,256] * W1chunk^T
        if (wid == 4) {
            TCF_AFTER();
            if (elect_one()) {
                const uint64_t bd = s ? w1d1 : w1d0;
#pragma unroll
                for (int ks = 0; ks < 16; ++ks) {
                    const int kc = ks >> 2, ki = ks & 3;
                    mma_f16_ss(tmem + TM_H, adesc + kc * 1024 + ki * 2,
                               bd + kc * 512 + ki * 2, IDESC1, (uint32_t)(ks > 0));
                }
                TC_COMMIT(sb + MB_G1);
            }
        }
        // 2) prefetch next weight chunk (overlaps GEMM1 on tensor pipe)
        if (i + 1 < CHUNKS) load_chunk(smem, t, i + 1, tid);
        FENCE_ASYNC();
        __syncthreads();
        // 3) epilogue: h -> gelu -> a2 (warps 0-3, one per TMEM subpartition)
        if (wid < 4) {
            MBAR_WAIT(sb + MB_G1, i & 1);
            TCF_AFTER();
            uint32_t rr[64];
            LDTM32(rr,      tmem + TM_H);
            LDTM32(rr + 32, tmem + TM_H + 32);
            TC_WAITLD();
            uint32_t aa[32];
            const float* bb = b1s + i * NC;
#pragma unroll
            for (int c = 0; c < 32; ++c) {
                float u0 = __uint_as_float(rr[2 * c])     + bb[2 * c];
                float u1 = __uint_as_float(rr[2 * c + 1]) + bb[2 * c + 1];
                float g0 = u0 * normcdff(u0);   // exact GELU
                float g1 = u1 * normcdff(u1);
                __half2 h = __floats2half2_rn(g0, g1);
                aa[c] = *(uint32_t*)&h;
            }
            if (i > 0) { MBAR_WAIT(sb + MB_G2, (i - 1) & 1); TCF_AFTER(); }
            STTM32(tmem + TM_A2 + warpoff, aa);
            TC_WAITST();
            TCF_BEFORE();
        }
        __syncthreads();
        // 4) GEMM2(i): out[128,256] += a2[128,64] * W2chunk^T
        if (wid == 4) {
            TCF_AFTER();
            if (elect_one()) {
                const uint64_t bd = s ? w2d1 : w2d0;
#pragma unroll
                for (int ks = 0; ks < 4; ++ks)
                    mma_f16_ts(tmem + TM_OUT, tmem + TM_A2 + ks * 8,
                               bd + ks * 2, IDESC2, (uint32_t)((i > 0) | (ks > 0)));
                TC_COMMIT(sb + MB_G2);
            }
        }
    }

    // final out epilogue
    if (wid < 4) {
        MBAR_WAIT(sb + MB_G2, (CHUNKS - 1) & 1);
        TCF_AFTER();
        float* orow = out + (((size_t)(mtile * MTILE + tid)) * TT + t) * DD;
#pragma unroll 1
        for (int g = 0; g < 8; ++g) {
            uint32_t ou[32];
            LDTM32(ou, tmem + TM_OUT + g * 32);
            TC_WAITLD();
#pragma unroll
            for (int q = 0; q < 8; ++q) {
                float4 v;
                v.x = __uint_as_float(ou[4 * q + 0]) + b2s[g * 32 + 4 * q + 0];
                v.y = __uint_as_float(ou[4 * q + 1]) + b2s[g * 32 + 4 * q + 1];
                v.z = __uint_as_float(ou[4 * q + 2]) + b2s[g * 32 + 4 * q + 2];
                v.w = __uint_as_float(ou[4 * q + 3]) + b2s[g * 32 + 4 * q + 3];
                *(float4*)(orow + g * 32 + q * 4) = v;
            }
        }
        TCF_BEFORE();
    }
    __syncthreads();
    if (wid == 4) TC_DEALLOC(tmem, 512);

#else
    // ---------------- WMMA fallback (plain sm_103 cubin) ----------------
    using namespace nvcuda;
    extern __shared__ __align__(1024) char smem[];
    const int tid  = threadIdx.x;
    const int wid  = tid >> 5;
    const int lane = tid & 31;
    const int t     = blockIdx.x >> 5;
    const int mtile = blockIdx.x & 31;

    __half* Xs  = (__half*)(smem + FB_X);   // [128][256] row-major
    __half* Hs  = (__half*)(smem + FB_H);   // [128][80]  row-major (64 used)
    float*  stg = (float*)(smem + FB_STG) + wid * (16 * 24); // per-warp 16x24

    // stage x tile fp32->fp16
    {
        const size_t bbase = (size_t)mtile * MTILE;
        for (int idx = tid; idx < MTILE * DD / 4; idx += 256) {
            int r = idx >> 6;
            int k = (idx & 63) * 4;
            float4 v = *(const float4*)(x + ((bbase + r) * TT + t) * DD + k);
            __half2 h0 = __floats2half2_rn(v.x, v.y);
            __half2 h1 = __floats2half2_rn(v.z, v.w);
            uint2 pk; pk.x = *(uint32_t*)&h0; pk.y = *(uint32_t*)&h1;
            *(uint2*)(Xs + r * 256 + k) = pk;
        }
    }
    __syncthreads();

    // 16 persistent out accumulators per warp: rows 16*wid..+15, cols 16j..+15
    wmma::fragment<wmma::accumulator, 16, 16, 16, float> cacc[16];
#pragma unroll
    for (int j = 0; j < 16; ++j) wmma::fill_fragment(cacc[j], 0.0f);

    const __half* w1t = g_W1T + (size_t)t * HH * DD;
    const __half* w2t = g_W2T + (size_t)t * DD * HH;
    const int row0 = 16 * wid;

#pragma unroll 1
    for (int i = 0; i < CHUNKS; ++i) {
        // GEMM1: h chunk rows row0..row0+15, 64 cols
#pragma unroll 1
        for (int j = 0; j < 4; ++j) {
            wmma::fragment<wmma::accumulator, 16, 16, 16, float> c1;
            wmma::fill_fragment(c1, 0.0f);
#pragma unroll
            for (int kk = 0; kk < 16; ++kk) {
                wmma::fragment<wmma::matrix_a, 16, 16, 16, __half, wmma::row_major> af;
                wmma::fragment<wmma::matrix_b, 16, 16, 16, __half, wmma::col_major> bf;
                wmma::load_matrix_sync(af, Xs + row0 * 256 + kk * 16, 256);
                wmma::load_matrix_sync(bf, w1t + (size_t)(i * NC + 16 * j) * DD + kk * 16, DD);
                wmma::mma_sync(c1, af, bf, c1);
            }
            wmma::store_matrix_sync(stg, c1, 24, wmma::mem_row_major);
            __syncwarp();
#pragma unroll
            for (int q = 0; q < 8; ++q) {
                int idx = lane * 8 + q;
                int r = idx >> 4, c = idx & 15;
                float u = stg[r * 24 + c] + b1[(size_t)t * HH + i * NC + 16 * j + c];
                Hs[(row0 + r) * 80 + 16 * j + c] = __float2half_rn(u * normcdff(u));
            }
            __syncwarp();
        }
        // GEMM2: out rows row0..+15 += h[16,64] * W2chunk
        wmma::fragment<wmma::matrix_a, 16, 16, 16, __half, wmma::row_major> a2[4];
#pragma unroll
        for (int kk = 0; kk < 4; ++kk)
            wmma::load_matrix_sync(a2[kk], Hs + row0 * 80 + kk * 16, 80);
#pragma unroll 1
        for (int j = 0; j < 16; ++j) {
#pragma unroll
            for (int kk = 0; kk < 4; ++kk) {
                wmma::fragment<wmma::matrix_b, 16, 16, 16, __half, wmma::col_major> bf;
                wmma::load_matrix_sync(bf, w2t + (size_t)(16 * j) * HH + i * NC + kk * 16, HH);
                wmma::mma_sync(cacc[j], a2[kk], bf, cacc[j]);
            }
        }
    }

    // writeout: +b2, fp32 out
#pragma unroll 1
    for (int j = 0; j < 16; ++j) {
        wmma::store_matrix_sync(stg, cacc[j], 24, wmma::mem_row_major);
        __syncwarp();
#pragma unroll
        for (int q = 0; q < 8; ++q) {
            int idx = lane * 8 + q;
            int r = idx >> 4, c = idx & 15;
            float val = stg[r * 24 + c] + b2[(size_t)t * DD + 16 * j + c];
            out[(((size_t)(mtile * MTILE + row0 + r)) * TT + t) * DD + 16 * j + c] = val;
        }
        __syncwarp();
    }
#endif
}

// ===================== launch =====================
extern "C" void kernel_launch(void* const* d_in, const int* in_sizes, int n_in,
                              void* d_out, int out_size) {
    const float* x  = (const float*)d_in[0];
    const float* W1 = (const float*)d_in[1];
    const float* b1 = (const float*)d_in[2];
    const float* W2 = (const float*)d_in[3];
    const float* b2 = (const float*)d_in[4];
    float* out = (float*)d_out;

    cudaFuncSetAttribute(fused_mlp, cudaFuncAttributeMaxDynamicSharedMemorySize, SMEM_BYTES);

    // pre-pass: transpose + cast weights to fp16 (plain kernel launches, capturable)
    tconvW1<<<dim3(HH / 32, DD / 32, TT), dim3(32, 8)>>>(W1);
    tconvW2<<<dim3(DD / 32, HH / 32, TT), dim3(32, 8)>>>(W2);

    // fused grouped MLP: 2048 CTAs (64 t-groups x 32 m-tiles)
    fused_mlp<<<TT * 32, 256, SMEM_BYTES>>>(x, b1, b2, out);
}